// round 1
// baseline (speedup 1.0000x reference)
#include <cuda_runtime.h>

#define NN 50000
#define NE 3200000

// Scratch (device globals — no allocation allowed)
__device__ float4 g_nodeF4[NN];     // pos.x, pos.y, cell, pad
__device__ float4 g_s[NN * 4];      // per-node folded source vector s[16]
__device__ float4 g_yacc[NN];       // sum over edges of m@W_out
__device__ float  g_degacc[NN];     // deg + 4096*consume_deg (exact ints)
__device__ double g_red[8];         // 0:velx 1:vely 2:border 3:dead 4:consumed 5:visible_food 6:food_dist

// ---------------- Kernel A: per-node prep + zeroing ----------------
__global__ void prep_kernel(const float* __restrict__ x,
                            const float* __restrict__ W_edge,
                            const float* __restrict__ W_src,
                            const float* __restrict__ b1,
                            int n)
{
    int i = blockIdx.x * blockDim.x + threadIdx.x;
    if (i == 0) {
        #pragma unroll
        for (int k = 0; k < 8; k++) g_red[k] = 0.0;
    }
    if (i >= n) return;

    float xv[10];
    #pragma unroll
    for (int c = 0; c < 10; c++) xv[c] = __ldg(&x[i * 10 + c]);
    float cell = xv[4];

    // s_j = b1_j + cell*W_edge[3][j] + sum_c x_c * W_src[c][j]
    #pragma unroll
    for (int q = 0; q < 4; q++) {
        float sv[4];
        #pragma unroll
        for (int jj = 0; jj < 4; jj++) {
            int j = q * 4 + jj;
            float acc = __ldg(&b1[j]) + cell * __ldg(&W_edge[3 * 16 + j]);
            #pragma unroll
            for (int c = 0; c < 10; c++)
                acc += xv[c] * __ldg(&W_src[c * 16 + j]);
            sv[jj] = acc;
        }
        g_s[i * 4 + q] = make_float4(sv[0], sv[1], sv[2], sv[3]);
    }
    g_nodeF4[i]  = make_float4(xv[0], xv[1], cell, 0.0f);
    g_yacc[i]    = make_float4(0.f, 0.f, 0.f, 0.f);
    g_degacc[i]  = 0.f;
}

// ---------------- Kernel B: edge kernel ----------------
__global__ void __launch_bounds__(128)
edge_kernel(const int* __restrict__ src,
            const int* __restrict__ dst,
            const float* __restrict__ W_edge,
            const float* __restrict__ W_out,
            int E)
{
    // Weights resident in registers (loaded once per thread, amortized over
    // the grid-stride loop; uniform addresses -> 1 line per LDG)
    float wA[16], wB[16], wC[16];
    float4 wO[16];
    #pragma unroll
    for (int j = 0; j < 16; j++) {
        wA[j] = __ldg(&W_edge[0 * 16 + j]);   // dist row
        wB[j] = __ldg(&W_edge[1 * 16 + j]);   // dx row
        wC[j] = __ldg(&W_edge[2 * 16 + j]);   // dy row
        wO[j] = __ldg((const float4*)&W_out[j * 4]);
    }

    const float4* __restrict__ nf = g_nodeF4;
    const float4* __restrict__ sp = g_s;

    float vf = 0.f;   // visible_food count
    float fd = 0.f;   // food dist sum

    int stride = gridDim.x * blockDim.x;
    for (int e = blockIdx.x * blockDim.x + threadIdx.x; e < E; e += stride) {
        int si = __ldg(&src[e]);
        int di = __ldg(&dst[e]);

        float4 ns = __ldg(&nf[si]);
        float4 nd = __ldg(&nf[di]);
        float4 s0 = __ldg(&sp[si * 4 + 0]);
        float4 s1 = __ldg(&sp[si * 4 + 1]);
        float4 s2 = __ldg(&sp[si * 4 + 2]);
        float4 s3 = __ldg(&sp[si * 4 + 3]);

        float dx = ns.x - nd.x;
        float dy = ns.y - nd.y;
        float d2 = __fadd_rn(__fadd_rn(__fmul_rn(dx, dx), __fmul_rn(dy, dy)), 1e-12f);
        float dist = sqrtf(d2);

        float sarr[16];
        *(float4*)&sarr[0]  = s0;
        *(float4*)&sarr[4]  = s1;
        *(float4*)&sarr[8]  = s2;
        *(float4*)&sarr[12] = s3;

        float y0 = 0.f, y1 = 0.f, y2 = 0.f, y3 = 0.f;
        #pragma unroll
        for (int j = 0; j < 16; j++) {
            float g = sarr[j] + dist * wA[j] + dx * wB[j] + dy * wC[j];
            float m = fmaxf(g, 0.f);
            y0 += m * wO[j].x;
            y1 += m * wO[j].y;
            y2 += m * wO[j].z;
            y3 += m * wO[j].w;
        }

        float4* yp = &g_yacc[di];
        asm volatile("red.global.add.v4.f32 [%0], {%1,%2,%3,%4};"
                     :: "l"(yp), "f"(y0), "f"(y1), "f"(y2), "f"(y3) : "memory");

        bool consume = (dist < 0.05f) && (ns.z == 1.0f) && (nd.z == 0.0f);
        atomicAdd(&g_degacc[di], consume ? 4097.0f : 1.0f);

        if (ns.z == 0.0f) { vf += 1.0f; fd += dist; }
    }

    // warp reduce, lane0 -> double atomics
    #pragma unroll
    for (int o = 16; o > 0; o >>= 1) {
        vf += __shfl_down_sync(0xffffffffu, vf, o);
        fd += __shfl_down_sync(0xffffffffu, fd, o);
    }
    if ((threadIdx.x & 31) == 0) {
        atomicAdd(&g_red[5], (double)vf);
        atomicAdd(&g_red[6], (double)fd);
    }
}

// ---------------- Kernel C: node finalize ----------------
__global__ void node_kernel(const float* __restrict__ x,
                            const float* __restrict__ noise,
                            const float* __restrict__ b2,
                            float* __restrict__ out,
                            int n, int keepBase)
{
    int i = blockIdx.x * blockDim.x + threadIdx.x;

    float velx = 0.f, vely = 0.f, border = 0.f, deadf = 0.f, consf = 0.f;

    if (i < n) {
        float4 y  = g_yacc[i];
        float pack = g_degacc[i];

        float xv[10];
        #pragma unroll
        for (int c = 0; c < 10; c++) xv[c] = __ldg(&x[i * 10 + c]);
        float cell = xv[4];
        float cm = (cell == 1.0f) ? 1.0f : 0.0f;

        float h0 = tanhf(y.x + __ldg(&b2[0])) * cm;
        float h1 = tanhf(y.y + __ldg(&b2[1])) * cm;
        float h2 = tanhf(y.z + __ldg(&b2[2])) * cm;
        float h3 = tanhf(y.w + __ldg(&b2[3])) * cm;

        float nvx = fminf(fmaxf(xv[2] + h0 * 0.005f, -0.02f), 0.02f);
        float nvy = fminf(fmaxf(xv[3] + h1 * 0.005f, -0.02f), 0.02f);
        float npx = xv[0] + nvx;
        float npy = xv[1] + nvy;

        float nzx = nvx + (__ldg(&noise[2 * i])     * 2.0f - 1.0f) * 0.004f * cm;
        float nzy = nvy + (__ldg(&noise[2 * i + 1]) * 2.0f - 1.0f) * 0.004f * cm;

        float* o = out + (size_t)i * 10;
        o[0] = npx; o[1] = npy; o[2] = nzx; o[3] = nzy; o[4] = cell;
        o[5] = h2;  o[6] = h3;  o[7] = xv[7]; o[8] = xv[8]; o[9] = xv[9];

        int pi = (int)pack;
        int deg  = pi & 4095;
        int cdeg = pi >> 12;
        bool dead     = (cell == 1.0f) && (deg < 3);
        bool consumed = (cell == 0.0f) && (cdeg >= 3);
        out[keepBase + i] = (dead || consumed) ? 0.0f : 1.0f;

        velx = fabsf(nvx);
        vely = fabsf(nvy);
        float apx = fabsf(npx);
        if (apx > 1.0f) border += logf(apx + 1e-6f);
        float apy = fabsf(npy);
        if (apy > 1.0f) border += logf(apy + 1e-6f);
        deadf = dead ? 1.0f : 0.0f;
        consf = consumed ? 1.0f : 0.0f;
    }

    #pragma unroll
    for (int o = 16; o > 0; o >>= 1) {
        velx   += __shfl_down_sync(0xffffffffu, velx,   o);
        vely   += __shfl_down_sync(0xffffffffu, vely,   o);
        border += __shfl_down_sync(0xffffffffu, border, o);
        deadf  += __shfl_down_sync(0xffffffffu, deadf,  o);
        consf  += __shfl_down_sync(0xffffffffu, consf,  o);
    }
    if ((threadIdx.x & 31) == 0) {
        atomicAdd(&g_red[0], (double)velx);
        atomicAdd(&g_red[1], (double)vely);
        atomicAdd(&g_red[2], (double)border);
        atomicAdd(&g_red[3], (double)deadf);
        atomicAdd(&g_red[4], (double)consf);
    }
}

// ---------------- Kernel D: scalar outputs ----------------
__global__ void final_kernel(float* __restrict__ out, int base, float invN)
{
    if (threadIdx.x == 0 && blockIdx.x == 0) {
        out[base + 0] = (float)g_red[0] * invN;   // velocity_bonus x (mean)
        out[base + 1] = (float)g_red[1] * invN;   // velocity_bonus y
        out[base + 2] = (float)g_red[2];          // border_cost
        out[base + 3] = (float)g_red[4];          // food_reward (consumed count)
        out[base + 4] = (float)g_red[3];          // dead_cost
        out[base + 5] = (float)g_red[5];          // visible_food
        out[base + 6] = (float)g_red[6];          // mean_food_dist (sum)
    }
}

extern "C" void kernel_launch(void* const* d_in, const int* in_sizes, int n_in,
                              void* d_out, int out_size)
{
    const float* x      = (const float*)d_in[0];
    const int*   src    = (const int*)  d_in[1];
    const int*   dst    = (const int*)  d_in[2];
    const float* noise  = (const float*)d_in[3];
    const float* W_edge = (const float*)d_in[4];
    const float* W_src  = (const float*)d_in[5];
    const float* b1     = (const float*)d_in[6];
    const float* W_out  = (const float*)d_in[7];
    const float* b2     = (const float*)d_in[8];

    int n = in_sizes[0] / 10;
    int E = in_sizes[1];
    float* out = (float*)d_out;

    int scalarBase = out_size - 7;
    int keepBase   = scalarBase - n;

    prep_kernel<<<(n + 255) / 256, 256>>>(x, W_edge, W_src, b1, n);
    edge_kernel<<<888, 128>>>(src, dst, W_edge, W_out, E);
    node_kernel<<<(n + 255) / 256, 256>>>(x, noise, b2, out, n, keepBase);
    final_kernel<<<1, 32>>>(out, scalarBase, 1.0f / (float)n);
}